// round 5
// baseline (speedup 1.0000x reference)
#include <cuda_runtime.h>

// Problem constants
#define CIN   256
#define TT    4096
#define BB    8
#define COUT  256
#define MM    1024          // 4 gates * COUT
#define KK    512           // CIN * 2 taps
// GEMM tiling
#define BM    128           // 4 gates x 32 oc
#define BN    128
#define BK    32
#define ASTRIDE 36          // BK + 4 pad -> conflict-free A frag loads
#define BSTRIDE 132         // BN + 4 pad -> conflict-free B frag loads
#define SEQ   (BB*COUT)     // 2048 sequences
#define SGATE (BB*COUT*TT)  // 8388608 elements per gate array

// Scratch (alloc-free rule: __device__ globals). 3 x 33.5MB.
__device__ float g_f [SGATE];
__device__ float g_iz[SGATE];
__device__ float g_o [SGATE];

__device__ __forceinline__ float sigm(float v)    { return 1.f / (1.f + __expf(-v)); }
__device__ __forceinline__ float tanh_acc(float v){ return 2.f / (1.f + __expf(-2.f*v)) - 1.f; }
__device__ __forceinline__ unsigned cvt_tf32(float v) {
    unsigned u; asm("cvt.rna.tf32.f32 %0, %1;" : "=r"(u) : "f"(v)); return u;
}

// ---------------------------------------------------------------------------
// Kernel 1: fused conv-GEMM (tf32 mma.sync) + bias + activations
//   Gates[m, n] = sum_k A[m,k] * B[k,n]
//   A[m,k]: W row-permuted so an M-tile holds all 4 gates for 32 oc.
//   B[k,n]: k<256 -> x[b, k, t-1] (0 at t=0), k>=256 -> x[b, k-256, t].
//   Epilogue stages activated gates through smem, writes f~, iz, o~ coalesced.
// ---------------------------------------------------------------------------
__global__ __launch_bounds__(256, 2)
void qrnn_gemm(const float* __restrict__ x,
               const float* __restrict__ W,
               const float* __restrict__ bias)
{
    __shared__ float As[BM * ASTRIDE];   // 4608 floats
    __shared__ float Bs[BK * BSTRIDE];   // 4224 floats
    __shared__ float bias_s[BM];

    const int tid    = threadIdx.x;
    const int lane   = tid & 31;
    const int wid    = tid >> 5;
    const int warp_m = wid >> 1;         // == gate index (0:Z 1:F 2:O 3:I)
    const int warp_n = wid & 1;
    const int g4     = lane >> 2;        // mma groupID
    const int t4     = lane & 3;         // mma threadID-in-group

    const int oc0 = blockIdx.y * 32;     // oc base of this M-tile
    const int n0  = blockIdx.x * BN;     // flattened (b,t) base
    const int b   = n0 >> 12;            // TT = 4096
    const int t0  = n0 & (TT - 1);

    if (tid < BM) {
        int src = (tid >> 5) * 256 + oc0 + (tid & 31);
        bias_s[tid] = bias[src];
    }

    float acc[2][8][4];
    #pragma unroll
    for (int im = 0; im < 2; im++)
        #pragma unroll
        for (int in = 0; in < 8; in++)
            #pragma unroll
            for (int ci = 0; ci < 4; ci++) acc[im][in][ci] = 0.f;

    for (int kt = 0; kt < KK / BK; kt++) {
        __syncthreads();
        const int k0 = kt * BK;
        // --- A tile: permuted W rows, tf32-rounded ---
        #pragma unroll
        for (int i = 0; i < 16; i++) {
            int id = tid + i * 256;
            int m = id >> 5, k = id & 31;
            int src = (m >> 5) * 256 + oc0 + (m & 31);
            int kk = k0 + k;
            float v = W[src * 512 + ((kk & 255) << 1) + (kk >> 8)];
            As[m * ASTRIDE + k] = __uint_as_float(cvt_tf32(v));
        }
        // --- B tile: x columns (tap0 shifted by -1, tap1 aligned) ---
        if (kt < 8) {
            #pragma unroll
            for (int i = 0; i < 16; i++) {
                int id = tid + i * 256;
                int kr = id >> 7, c = id & 127;
                int tg = t0 + c - 1;
                float v = (tg >= 0) ? x[(b * CIN + k0 + kr) * TT + tg] : 0.f;
                Bs[kr * BSTRIDE + c] = __uint_as_float(cvt_tf32(v));
            }
        } else {
            #pragma unroll
            for (int i = 0; i < 16; i++) {
                int id = tid + i * 256;
                int kr = id >> 7, c = id & 127;
                float v = x[(b * CIN + (k0 - 256) + kr) * TT + t0 + c];
                Bs[kr * BSTRIDE + c] = __uint_as_float(cvt_tf32(v));
            }
        }
        __syncthreads();
        // --- compute: 4 k-subs x (2x8) m16n8k8 tf32 mmas per warp ---
        #pragma unroll
        for (int s = 0; s < 4; s++) {
            unsigned af[2][4];
            #pragma unroll
            for (int im = 0; im < 2; im++) {
                int row = warp_m * 32 + im * 16 + g4;
                af[im][0] = __float_as_uint(As[ row      * ASTRIDE + s*8 + t4    ]);
                af[im][1] = __float_as_uint(As[(row + 8) * ASTRIDE + s*8 + t4    ]);
                af[im][2] = __float_as_uint(As[ row      * ASTRIDE + s*8 + t4 + 4]);
                af[im][3] = __float_as_uint(As[(row + 8) * ASTRIDE + s*8 + t4 + 4]);
            }
            unsigned bf[8][2];
            #pragma unroll
            for (int in = 0; in < 8; in++) {
                int col = warp_n * 64 + in * 8 + g4;
                bf[in][0] = __float_as_uint(Bs[(s*8 + t4    ) * BSTRIDE + col]);
                bf[in][1] = __float_as_uint(Bs[(s*8 + t4 + 4) * BSTRIDE + col]);
            }
            #pragma unroll
            for (int im = 0; im < 2; im++)
                #pragma unroll
                for (int in = 0; in < 8; in++) {
                    asm volatile(
                        "mma.sync.aligned.m16n8k8.row.col.f32.tf32.tf32.f32 "
                        "{%0,%1,%2,%3}, {%4,%5,%6,%7}, {%8,%9}, {%0,%1,%2,%3};\n"
                        : "+f"(acc[im][in][0]), "+f"(acc[im][in][1]),
                          "+f"(acc[im][in][2]), "+f"(acc[im][in][3])
                        : "r"(af[im][0]), "r"(af[im][1]), "r"(af[im][2]), "r"(af[im][3]),
                          "r"(bf[in][0]), "r"(bf[in][1]));
                }
        }
    }
    __syncthreads();

    // ---- Epilogue: activations + cross-gate combine through smem staging ----
    // Round 1: Z -> tanh into As, I -> sigmoid into Bs; then iz = z*i.
    if (warp_m == 0 || warp_m == 3) {
        float* St = (warp_m == 0) ? As : Bs;
        #pragma unroll
        for (int im = 0; im < 2; im++)
            #pragma unroll
            for (int in = 0; in < 8; in++)
                #pragma unroll
                for (int ci = 0; ci < 4; ci++) {
                    int r  = im * 16 + g4 + ((ci >> 1) << 3);
                    int cc = warp_n * 64 + in * 8 + (t4 << 1) + (ci & 1);
                    float v = acc[im][in][ci] + bias_s[warp_m * 32 + r];
                    v = (warp_m == 0) ? tanh_acc(v) : sigm(v);
                    St[r * BSTRIDE + cc] = v;
                }
    }
    __syncthreads();
    #pragma unroll
    for (int i = 0; i < 16; i++) {
        int e = tid + i * 256;
        int r = e >> 7, cc = e & 127;
        float izv = As[r * BSTRIDE + cc] * Bs[r * BSTRIDE + cc];
        g_iz[(b * COUT + oc0 + r) * TT + t0 + cc] = izv;
    }
    __syncthreads();
    // Round 2: F -> sigmoid into As, O -> sigmoid into Bs.
    if (warp_m == 1 || warp_m == 2) {
        float* St = (warp_m == 1) ? As : Bs;
        #pragma unroll
        for (int im = 0; im < 2; im++)
            #pragma unroll
            for (int in = 0; in < 8; in++)
                #pragma unroll
                for (int ci = 0; ci < 4; ci++) {
                    int r  = im * 16 + g4 + ((ci >> 1) << 3);
                    int cc = warp_n * 64 + in * 8 + (t4 << 1) + (ci & 1);
                    float v = sigm(acc[im][in][ci] + bias_s[warp_m * 32 + r]);
                    St[r * BSTRIDE + cc] = v;
                }
    }
    __syncthreads();
    #pragma unroll
    for (int i = 0; i < 16; i++) {
        int e = tid + i * 256;
        int r = e >> 7, cc = e & 127;
        int gidx = (b * COUT + oc0 + r) * TT + t0 + cc;
        g_f[gidx] = As[r * BSTRIDE + cc];
        g_o[gidx] = Bs[r * BSTRIDE + cc];
    }
}

// ---------------------------------------------------------------------------
// Kernel 2: linear recurrence scan. One block (128 thr) per (b, oc) sequence.
//   c_t = f_t * c_{t-1} + iz_t ;  H_t = o_t * c_t
//   Thread-local 32-step segments, pair (a = prod f, b = local c) composed via
//   warp shfl scan + cross-warp combine. smem padded stride-33 (conflict-free).
// ---------------------------------------------------------------------------
__global__ __launch_bounds__(128)
void qrnn_scan(float* __restrict__ out)
{
    __shared__ float sf[TT + TT / 32];   // 4224
    __shared__ float sz[TT + TT / 32];
    __shared__ float wa[4], wb[4];

    const int tid  = threadIdx.x;
    const int lane = tid & 31;
    const int wrp  = tid >> 5;
    const int base = blockIdx.x * TT;

    for (int i = tid; i < TT; i += 128) {
        int p = i + (i >> 5);
        sf[p] = g_f [base + i];
        sz[p] = g_iz[base + i];
    }
    __syncthreads();

    const int s0 = tid * 33;             // padded base of this thread's chunk
    float a = 1.f, bb = 0.f;
    #pragma unroll
    for (int j = 0; j < 32; j++) {
        float f = sf[s0 + j], iz = sz[s0 + j];
        a *= f;
        bb = f * bb + iz;
    }
    // warp inclusive scan of (a, b) pairs: combine(earlier, cur) = (a*a_e, a*b_e + b)
    #pragma unroll
    for (int d = 1; d < 32; d <<= 1) {
        float ua = __shfl_up_sync(0xffffffffu, a,  d);
        float ub = __shfl_up_sync(0xffffffffu, bb, d);
        if (lane >= d) { bb = a * ub + bb; a = a * ua; }
    }
    if (lane == 31) { wa[wrp] = a; wb[wrp] = bb; }
    __syncthreads();
    // exclusive cross-warp prefix (<= 3 serial combines)
    float pa = 1.f, pb = 0.f;
    for (int w = 0; w < wrp; w++) { pb = wa[w] * pb + wb[w]; pa = wa[w] * pa; }
    // lane-exclusive from inclusive
    float ea = __shfl_up_sync(0xffffffffu, a,  1);
    float eb = __shfl_up_sync(0xffffffffu, bb, 1);
    if (lane == 0) { ea = 1.f; eb = 0.f; }
    float c = ea * pb + eb;              // c before this chunk (c_init = 0)

    #pragma unroll
    for (int j = 0; j < 32; j++) {
        float f = sf[s0 + j], iz = sz[s0 + j];
        c = f * c + iz;
        sf[s0 + j] = c;                  // overwrite f (consumed) with c
    }
    __syncthreads();
    for (int i = tid; i < TT; i += 128) {
        int p = i + (i >> 5);
        out[base + i] = g_o[base + i] * sf[p];
    }
}

extern "C" void kernel_launch(void* const* d_in, const int* in_sizes, int n_in,
                              void* d_out, int out_size)
{
    const float* x    = (const float*)d_in[0];  // [8, 256, 4096]
    const float* W    = (const float*)d_in[1];  // [1024, 256, 2]
    const float* bias = (const float*)d_in[2];  // [1024]
    float* out = (float*)d_out;                 // [8, 256, 4096] fp32

    dim3 ggrid(BB * TT / BN, MM / BM);          // (256, 8)
    qrnn_gemm<<<ggrid, 256>>>(x, W, bias);
    qrnn_scan<<<SEQ, 128>>>(out);
}

// round 7
// speedup vs baseline: 1.7165x; 1.7165x over previous
#include <cuda_runtime.h>
#include <cstdint>

// ---------------- problem constants ----------------
#define TT      4096
#define CIN     256
#define COUT    256
#define BBATCH  8
#define SGATE   (BBATCH*COUT*TT)     // 8388608

// GEMM tiling
#define BM      128
#define BN      128
#define BK      32
#define NKT     16                   // K=512 / 32
#define RSTRIDE 40                   // smem row stride (floats), conflict-free LDS.64
#define STAGEF  10240                // floats per stage: A 128*40 + B 128*40
#define GEMM_SMEM (2*STAGEF*4)       // 81920 bytes

// ---------------- scratch (__device__ globals; alloc-free rule) -------------
__device__ __align__(128) float g_f [SGATE];
__device__ __align__(128) float g_iz[SGATE];
__device__ __align__(128) float g_o [SGATE];
__device__ __align__(128) float xT  [(size_t)BBATCH*TT*CIN];   // [b][t][cin'] tf32-rna, sigma-perm
__device__ __align__(128) float Wp  [8*16*BM*BK];              // [y][kt][m][k'] tf32-rna

// ---------------- helpers ----------------
__device__ __forceinline__ float sigm(float v)    { return 1.f / (1.f + __expf(-v)); }
__device__ __forceinline__ float tanh_acc(float v){ return 2.f / (1.f + __expf(-2.f*v)) - 1.f; }
__device__ __forceinline__ float rna_tf32(float v) {
    unsigned u; asm("cvt.rna.tf32.f32 %0, %1;" : "=r"(u) : "f"(v));
    return __uint_as_float(u);
}
__device__ __forceinline__ uint32_t smem_u32(const void* p) {
    uint32_t a;
    asm("{ .reg .u64 t; cvta.to.shared.u64 t, %1; cvt.u32.u64 %0, t; }" : "=r"(a) : "l"(p));
    return a;
}
// sigma permutation within 8-groups: j -> (j>>1) + (j&1)*4  == [0,4,1,5,2,6,3,7]
__device__ __forceinline__ int sig8(int j) { return ((j & 7) >> 1) + ((j & 1) << 2); }

// ---------------------------------------------------------------------------
// Pre-kernel 1: x [b][cin][t] -> xT [b][t][cin'] (transpose + rna + sigma-perm)
// ---------------------------------------------------------------------------
__global__ __launch_bounds__(256)
void k_xprep(const float* __restrict__ x)
{
    __shared__ float s[32][33];
    const int t0 = blockIdx.x * 32, c0 = blockIdx.y * 32, b = blockIdx.z;
    const int lane = threadIdx.x & 31;

    #pragma unroll
    for (int rr = threadIdx.x >> 5; rr < 32; rr += 8)
        s[rr][lane] = x[((size_t)(b * CIN + c0 + rr)) * TT + t0 + lane];
    __syncthreads();

    #pragma unroll
    for (int i = 0; i < 4; i++) {
        int idx  = threadIdx.x + i * 256;
        int trow = idx >> 5, c = idx & 31;
        int cs   = (c & ~7) | sig8(c);
        xT[((size_t)(b * TT + t0 + trow)) * CIN + c0 + c] = rna_tf32(s[cs][trow]);
    }
}

// ---------------------------------------------------------------------------
// Pre-kernel 2: W [1024][256][2] -> Wp [y][kt][m][k'] (permute + rna + sigma)
//   m row = gate(m>>5)*256 + y*32 + (m&31); k = kt*32+kin; kin' sigma-permuted.
//   kk<256 -> W[..][kk][0] (pairs x[t-1]); kk>=256 -> W[..][kk-256][1] (x[t]).
// ---------------------------------------------------------------------------
__global__ __launch_bounds__(256)
void k_wprep(const float* __restrict__ W)
{
    const int kt = blockIdx.x, y = blockIdx.y;
    float* dst = Wp + ((y * NKT + kt) << 12);
    for (int i = threadIdx.x; i < 4096; i += 256) {
        int m = i >> 5, j = i & 31;
        int kin = (j & ~7) | sig8(j);
        int kk  = kt * 32 + kin;
        int wrow = (m >> 5) * 256 + y * 32 + (m & 31);
        dst[i] = rna_tf32(W[wrow * 512 + ((kk & 255) << 1) + (kk >> 8)]);
    }
}

// ---------------------------------------------------------------------------
// Kernel 3: pipelined tf32 mma.sync GEMM + fused activations.
//   Double-buffered cp.async (2 stages), LDS.64 fragment loads (sigma-paired).
// ---------------------------------------------------------------------------
__global__ __launch_bounds__(256, 2)
void qrnn_gemm(const float* __restrict__ bias)
{
    extern __shared__ float smem[];
    __shared__ float bias_s[BM];

    const int tid    = threadIdx.x;
    const int lane   = tid & 31;
    const int wid    = tid >> 5;
    const int warp_m = wid >> 1;         // gate index 0:Z 1:F 2:O 3:I
    const int warp_n = wid & 1;
    const int g4     = lane >> 2;
    const int t4     = lane & 3;

    const int y   = blockIdx.y;
    const int oc0 = y * 32;
    const int b   = blockIdx.x >> 5;
    const int t0  = (blockIdx.x & 31) * BN;

    if (tid < BM)
        bias_s[tid] = bias[(tid >> 5) * 256 + oc0 + (tid & 31)];

    float acc[2][8][4];
    #pragma unroll
    for (int im = 0; im < 2; im++)
        #pragma unroll
        for (int in = 0; in < 8; in++)
            #pragma unroll
            for (int ci = 0; ci < 4; ci++) acc[im][in][ci] = 0.f;

    // per-thread load coords (16B units; 1024 units per matrix per tile)
    const int r_a  = tid >> 1;                 // handled via loop below
    (void)r_a;

    // ---- prefetch lambda-ish macro ----
    #define PREFETCH(KT, BUF) do {                                              \
        const int kt_ = (KT);                                                   \
        float* ad_ = smem + (BUF) * STAGEF;                                     \
        float* bd_ = ad_ + BM * RSTRIDE;                                        \
        const float* wsrc_ = Wp + ((y * NKT + kt_) << 12);                      \
        const int tap_  = (kt_ < 8) ? 1 : 0;                                    \
        const int cin0_ = (kt_ & 7) * 32;                                       \
        const float* xb_ = xT + ((size_t)(b * TT + t0 - tap_) * CIN + cin0_);   \
        _Pragma("unroll")                                                       \
        for (int i_ = 0; i_ < 4; i_++) {                                        \
            int u_ = tid + i_ * 256;                                            \
            int r_ = u_ >> 3, cu_ = u_ & 7;                                     \
            uint32_t da_ = smem_u32(ad_ + r_ * RSTRIDE + cu_ * 4);              \
            asm volatile("cp.async.cg.shared.global [%0], [%1], 16;"            \
                :: "r"(da_), "l"(wsrc_ + u_ * 4) : "memory");                   \
            uint32_t db_ = smem_u32(bd_ + r_ * RSTRIDE + cu_ * 4);              \
            int sz_ = (t0 + r_ - tap_ >= 0) ? 16 : 0;                           \
            asm volatile("cp.async.cg.shared.global [%0], [%1], 16, %2;"        \
                :: "r"(db_), "l"(xb_ + (size_t)r_ * CIN + cu_ * 4), "r"(sz_)    \
                : "memory");                                                    \
        }                                                                       \
        asm volatile("cp.async.commit_group;" ::: "memory");                    \
    } while (0)

    PREFETCH(0, 0);

    #pragma unroll 1
    for (int kt = 0; kt < NKT; kt++) {
        const int buf = kt & 1;
        if (kt < NKT - 1) PREFETCH(kt + 1, buf ^ 1);
        if (kt < NKT - 1) asm volatile("cp.async.wait_group 1;" ::: "memory");
        else              asm volatile("cp.async.wait_group 0;" ::: "memory");
        __syncthreads();

        const float* As = smem + buf * STAGEF;
        const float* Bs = As + BM * RSTRIDE;
        const int row0 = warp_m * 32 + g4;
        const int col0 = warp_n * 64 + g4;

        #pragma unroll
        for (int s = 0; s < 4; s++) {
            const int ko = s * 8 + 2 * t4;
            float2 a0 = *(const float2*)(As + (row0     ) * RSTRIDE + ko);
            float2 a1 = *(const float2*)(As + (row0 +  8) * RSTRIDE + ko);
            float2 a2 = *(const float2*)(As + (row0 + 16) * RSTRIDE + ko);
            float2 a3 = *(const float2*)(As + (row0 + 24) * RSTRIDE + ko);
            float2 bf[8];
            #pragma unroll
            for (int in = 0; in < 8; in++)
                bf[in] = *(const float2*)(Bs + (col0 + in * 8) * RSTRIDE + ko);
            #pragma unroll
            for (int in = 0; in < 8; in++) {
                asm volatile(
                    "mma.sync.aligned.m16n8k8.row.col.f32.tf32.tf32.f32 "
                    "{%0,%1,%2,%3}, {%4,%5,%6,%7}, {%8,%9}, {%0,%1,%2,%3};\n"
                    : "+f"(acc[0][in][0]), "+f"(acc[0][in][1]),
                      "+f"(acc[0][in][2]), "+f"(acc[0][in][3])
                    : "r"(__float_as_uint(a0.x)), "r"(__float_as_uint(a1.x)),
                      "r"(__float_as_uint(a0.y)), "r"(__float_as_uint(a1.y)),
                      "r"(__float_as_uint(bf[in].x)), "r"(__float_as_uint(bf[in].y)));
                asm volatile(
                    "mma.sync.aligned.m16n8k8.row.col.f32.tf32.tf32.f32 "
                    "{%0,%1,%2,%3}, {%4,%5,%6,%7}, {%8,%9}, {%0,%1,%2,%3};\n"
                    : "+f"(acc[1][in][0]), "+f"(acc[1][in][1]),
                      "+f"(acc[1][in][2]), "+f"(acc[1][in][3])
                    : "r"(__float_as_uint(a2.x)), "r"(__float_as_uint(a3.x)),
                      "r"(__float_as_uint(a2.y)), "r"(__float_as_uint(a3.y)),
                      "r"(__float_as_uint(bf[in].x)), "r"(__float_as_uint(bf[in].y)));
            }
        }
        __syncthreads();
    }
    #undef PREFETCH

    // ---- Epilogue (R4-proven): activations + Z*I combine via smem staging ----
    #define BSTRIDE 132
    float* Sa = smem;                // 32*132 floats
    float* Sb = smem + 32 * BSTRIDE;

    if (warp_m == 0 || warp_m == 3) {
        float* St = (warp_m == 0) ? Sa : Sb;
        #pragma unroll
        for (int im = 0; im < 2; im++)
            #pragma unroll
            for (int in = 0; in < 8; in++)
                #pragma unroll
                for (int ci = 0; ci < 4; ci++) {
                    int r  = im * 16 + g4 + ((ci >> 1) << 3);
                    int cc = warp_n * 64 + in * 8 + (t4 << 1) + (ci & 1);
                    float v = acc[im][in][ci] + bias_s[warp_m * 32 + r];
                    v = (warp_m == 0) ? tanh_acc(v) : sigm(v);
                    St[r * BSTRIDE + cc] = v;
                }
    }
    __syncthreads();
    #pragma unroll
    for (int i = 0; i < 16; i++) {
        int e = tid + i * 256;
        int r = e >> 7, cc = e & 127;
        float izv = Sa[r * BSTRIDE + cc] * Sb[r * BSTRIDE + cc];
        g_iz[((size_t)(b * COUT + oc0 + r)) * TT + t0 + cc] = izv;
    }
    __syncthreads();
    if (warp_m == 1 || warp_m == 2) {
        float* St = (warp_m == 1) ? Sa : Sb;
        #pragma unroll
        for (int im = 0; im < 2; im++)
            #pragma unroll
            for (int in = 0; in < 8; in++)
                #pragma unroll
                for (int ci = 0; ci < 4; ci++) {
                    int r  = im * 16 + g4 + ((ci >> 1) << 3);
                    int cc = warp_n * 64 + in * 8 + (t4 << 1) + (ci & 1);
                    float v = sigm(acc[im][in][ci] + bias_s[warp_m * 32 + r]);
                    St[r * BSTRIDE + cc] = v;
                }
    }
    __syncthreads();
    #pragma unroll
    for (int i = 0; i < 16; i++) {
        int e = tid + i * 256;
        int r = e >> 7, cc = e & 127;
        size_t gidx = ((size_t)(b * COUT + oc0 + r)) * TT + t0 + cc;
        g_f[gidx] = Sa[r * BSTRIDE + cc];
        g_o[gidx] = Sb[r * BSTRIDE + cc];
    }
    #undef BSTRIDE
}

// ---------------------------------------------------------------------------
// Kernel 4: linear recurrence scan, register-resident chunks (no data smem).
//   One block (128 thr) per sequence; thread t owns elements [t*32, t*32+32).
// ---------------------------------------------------------------------------
__global__ __launch_bounds__(128)
void qrnn_scan(float* __restrict__ out)
{
    __shared__ float wa[4], wb[4];

    const int tid  = threadIdx.x;
    const int lane = tid & 31;
    const int wrp  = tid >> 5;
    const size_t my = (size_t)blockIdx.x * TT + tid * 32;

    float f[32], z[32];
    #pragma unroll
    for (int j = 0; j < 8; j++) {
        float4 vf = ((const float4*)(g_f  + my))[j];
        float4 vz = ((const float4*)(g_iz + my))[j];
        f[j*4+0] = vf.x; f[j*4+1] = vf.y; f[j*4+2] = vf.z; f[j*4+3] = vf.w;
        z[j*4+0] = vz.x; z[j*4+1] = vz.y; z[j*4+2] = vz.z; z[j*4+3] = vz.w;
    }

    float a = 1.f, bb = 0.f;
    #pragma unroll
    for (int j = 0; j < 32; j++) { a *= f[j]; bb = f[j] * bb + z[j]; }

    #pragma unroll
    for (int d = 1; d < 32; d <<= 1) {
        float ua = __shfl_up_sync(0xffffffffu, a,  d);
        float ub = __shfl_up_sync(0xffffffffu, bb, d);
        if (lane >= d) { bb = a * ub + bb; a = a * ua; }
    }
    if (lane == 31) { wa[wrp] = a; wb[wrp] = bb; }
    __syncthreads();
    float pb = 0.f;
    #pragma unroll
    for (int w = 0; w < 3; w++)
        if (w < wrp) pb = wa[w] * pb + wb[w];
    float ea = __shfl_up_sync(0xffffffffu, a,  1);
    float eb = __shfl_up_sync(0xffffffffu, bb, 1);
    if (lane == 0) { ea = 1.f; eb = 0.f; }
    float c = ea * pb + eb;            // carry into this chunk (c_init = 0)

    #pragma unroll
    for (int j = 0; j < 32; j++) { c = f[j] * c + z[j]; f[j] = c; }

    #pragma unroll
    for (int j = 0; j < 8; j++) {
        float4 vo = ((const float4*)(g_o + my))[j];
        float4 r;
        r.x = vo.x * f[j*4+0]; r.y = vo.y * f[j*4+1];
        r.z = vo.z * f[j*4+2]; r.w = vo.w * f[j*4+3];
        ((float4*)(out + my))[j] = r;
    }
}

extern "C" void kernel_launch(void* const* d_in, const int* in_sizes, int n_in,
                              void* d_out, int out_size)
{
    const float* x    = (const float*)d_in[0];  // [8, 256, 4096]
    const float* W    = (const float*)d_in[1];  // [1024, 256, 2]
    const float* bias = (const float*)d_in[2];  // [1024]
    float* out = (float*)d_out;                 // [8, 256, 4096]

    static int smem_set = 0;
    if (!smem_set) {
        cudaFuncSetAttribute(qrnn_gemm, cudaFuncAttributeMaxDynamicSharedMemorySize, GEMM_SMEM);
        smem_set = 1;
    }

    k_xprep<<<dim3(TT / 32, CIN / 32, BBATCH), 256>>>(x);
    k_wprep<<<dim3(NKT, 8), 256>>>(W);
    qrnn_gemm<<<dim3(BBATCH * TT / BN, 8), 256, GEMM_SMEM>>>(bias);
    qrnn_scan<<<BBATCH * COUT, 128>>>(out);
}

// round 9
// speedup vs baseline: 2.4558x; 1.4307x over previous
#include <cuda_runtime.h>
#include <cuda_fp16.h>
#include <cstdint>

// ---------------- problem constants ----------------
#define TT      4096
#define CIN     256
#define COUT    256
#define BBATCH  8
#define SGATE   (BBATCH*COUT*TT)     // 8388608

// GEMM tiling
#define BM      128
#define BN      128
#define BK      32
#define NKT     16                    // K=512 / 32
#define ROWB    96                    // smem row stride bytes (24 words) conflict-free
#define STAGEB  (2*BM*ROWB)           // 24576 bytes per stage (A + B)
#define GEMM_SMEM (2*STAGEB)          // 49152

// ---------------- scratch (__device__ globals; alloc-free rule) -------------
__device__ __align__(128) float  g_f [SGATE];
__device__ __align__(128) float  g_iz[SGATE];
__device__ __align__(128) float  g_o [SGATE];
__device__ __align__(128) __half xT  [(size_t)BBATCH*TT*CIN];   // [b][t][cin'] perm fp16
__device__ __align__(128) __half Wp  [8*NKT*BM*BK];             // [y][kt][m][k'] perm fp16

// ---------------- helpers ----------------
__device__ __forceinline__ float sigm(float v)    { return 1.f / (1.f + __expf(-v)); }
__device__ __forceinline__ float tanh_acc(float v){ return 2.f / (1.f + __expf(-2.f*v)) - 1.f; }
__device__ __forceinline__ uint32_t smem_u32(const void* p) {
    uint32_t a;
    asm("{ .reg .u64 t; cvta.to.shared.u64 t, %1; cvt.u32.u64 %0, t; }" : "=r"(a) : "l"(p));
    return a;
}
// inverse of the frag interleave: dest slot j' (0..15) -> source k-in-16
__device__ __forceinline__ int invp(int jp) {
    int t4 = jp >> 2, pos = jp & 3;
    return 2 * t4 + (pos & 1) + 8 * (pos >> 1);
}

// ---------------------------------------------------------------------------
// Pre-kernel 1: x [b][cin][t] -> xT [b][t][cin'] fp16, k-interleaved per 16
// ---------------------------------------------------------------------------
__global__ __launch_bounds__(256)
void k_xprep(const float* __restrict__ x)
{
    __shared__ float s[32][33];
    const int t0 = blockIdx.x * 32, c0 = blockIdx.y * 32, b = blockIdx.z;
    const int lane = threadIdx.x & 31;

    #pragma unroll
    for (int rr = threadIdx.x >> 5; rr < 32; rr += 8)
        s[rr][lane] = x[((size_t)(b * CIN + c0 + rr)) * TT + t0 + lane];
    __syncthreads();

    #pragma unroll
    for (int i = 0; i < 2; i++) {
        int sl = threadIdx.x + i * 256;       // 512 u32 slots: 32 trow x 16
        int trow = sl >> 4, ms = sl & 15;
        int grp = ms >> 3, jp = (2 * ms) & 15;
        int c0s = grp * 16 + invp(jp);
        int c1s = grp * 16 + invp(jp + 1);
        __half2 v = __floats2half2_rn(s[c0s][trow], s[c1s][trow]);
        ((__half2*)xT)[(((size_t)(b * TT + t0 + trow)) * CIN + c0 >> 1) + ms] = v;
    }
}

// ---------------------------------------------------------------------------
// Pre-kernel 2: W [1024][256][2] -> Wp [y][kt][m][k'] fp16 (permute+interleave)
//   m row = gate(m>>5)*256 + y*32 + (m&31); kk = kt*32 + k_local.
//   kk<256 -> W[..][kk][0] (pairs x[t-1]); kk>=256 -> W[..][kk-256][1] (x[t]).
// ---------------------------------------------------------------------------
__global__ __launch_bounds__(256)
void k_wprep(const float* __restrict__ W)
{
    const int kt = blockIdx.x, y = blockIdx.y;
    __half2* dst = (__half2*)(Wp + ((size_t)(y * NKT + kt) << 12));
    #pragma unroll
    for (int i = 0; i < 8; i++) {
        int sl = threadIdx.x + i * 256;       // 2048 u32 slots: 128 m x 16
        int m = sl >> 4, ms = sl & 15;
        int grp = ms >> 3, jp = (2 * ms) & 15;
        int wrow = (m >> 5) * 256 + y * 32 + (m & 31);
        int kk0 = kt * 32 + grp * 16 + invp(jp);
        int kk1 = kt * 32 + grp * 16 + invp(jp + 1);
        float v0 = W[wrow * 512 + ((kk0 & 255) << 1) + (kk0 >> 8)];
        float v1 = W[wrow * 512 + ((kk1 & 255) << 1) + (kk1 >> 8)];
        dst[sl] = __floats2half2_rn(v0, v1);
    }
}

// ---------------------------------------------------------------------------
// Kernel 3: pipelined fp16 mma.sync m16n8k16 GEMM + fused activations.
// ---------------------------------------------------------------------------
__global__ __launch_bounds__(256, 2)
void qrnn_gemm(const float* __restrict__ bias)
{
    extern __shared__ char smem[];
    __shared__ float bias_s[BM];

    const int tid    = threadIdx.x;
    const int lane   = tid & 31;
    const int wid    = tid >> 5;
    const int warp_m = wid >> 1;         // gate 0:Z 1:F 2:O 3:I
    const int warp_n = wid & 1;
    const int g4     = lane >> 2;
    const int t4     = lane & 3;

    const int y   = blockIdx.y;
    const int oc0 = y * 32;
    const int b   = blockIdx.x >> 5;
    const int t0  = (blockIdx.x & 31) * BN;

    if (tid < BM)
        bias_s[tid] = bias[(tid >> 5) * 256 + oc0 + (tid & 31)];

    float acc[2][8][4];
    #pragma unroll
    for (int im = 0; im < 2; im++)
        #pragma unroll
        for (int in = 0; in < 8; in++)
            #pragma unroll
            for (int ci = 0; ci < 4; ci++) acc[im][in][ci] = 0.f;

    // per-thread cp.async coords: 1024 16B chunks (A 512 + B 512), 4 per thread
    #define PREFETCH(KT, BUF) do {                                              \
        const int kt_ = (KT);                                                   \
        char* stA_ = smem + (BUF) * STAGEB;                                     \
        char* stB_ = stA_ + BM * ROWB;                                          \
        const __half* wc_ = Wp + ((size_t)(y * NKT + kt_) << 12);               \
        const int tap_  = (kt_ < 8) ? 1 : 0;                                    \
        const int cin0_ = (kt_ & 7) * 32;                                       \
        _Pragma("unroll")                                                       \
        for (int i_ = 0; i_ < 4; i_++) {                                        \
            int u_ = tid + i_ * 256;                                            \
            int idx_ = u_ & 511, r_ = idx_ >> 2, cu_ = idx_ & 3;                \
            if (u_ < 512) {                                                     \
                uint32_t da_ = smem_u32(stA_ + r_ * ROWB + cu_ * 16);           \
                asm volatile("cp.async.cg.shared.global [%0], [%1], 16;"        \
                    :: "r"(da_), "l"(wc_ + r_ * 32 + cu_ * 8) : "memory");      \
            } else {                                                            \
                uint32_t db_ = smem_u32(stB_ + r_ * ROWB + cu_ * 16);           \
                int tg_ = t0 + r_ - tap_;                                       \
                int sz_ = (tg_ >= 0) ? 16 : 0;                                  \
                const __half* src_ = xT + ((size_t)(b * TT + tg_) * CIN + cin0_ + cu_ * 8); \
                asm volatile("cp.async.cg.shared.global [%0], [%1], 16, %2;"    \
                    :: "r"(db_), "l"(src_), "r"(sz_) : "memory");               \
            }                                                                   \
        }                                                                       \
        asm volatile("cp.async.commit_group;" ::: "memory");                    \
    } while (0)

    PREFETCH(0, 0);

    #pragma unroll 1
    for (int kt = 0; kt < NKT; kt++) {
        const int buf = kt & 1;
        if (kt < NKT - 1) {
            PREFETCH(kt + 1, buf ^ 1);
            asm volatile("cp.async.wait_group 1;" ::: "memory");
        } else {
            asm volatile("cp.async.wait_group 0;" ::: "memory");
        }
        __syncthreads();

        const char* As = smem + buf * STAGEB;
        const char* Bs = As + BM * ROWB;
        const int row0 = warp_m * 32 + g4;
        const int col0 = warp_n * 64 + g4;

        #pragma unroll
        for (int s = 0; s < 2; s++) {
            const int kb = s * 32 + t4 * 8;
            uint2 a00 = *(const uint2*)(As + (row0     ) * ROWB + kb);
            uint2 a08 = *(const uint2*)(As + (row0 +  8) * ROWB + kb);
            uint2 a16 = *(const uint2*)(As + (row0 + 16) * ROWB + kb);
            uint2 a24 = *(const uint2*)(As + (row0 + 24) * ROWB + kb);
            uint2 bv[8];
            #pragma unroll
            for (int in = 0; in < 8; in++)
                bv[in] = *(const uint2*)(Bs + (col0 + in * 8) * ROWB + kb);
            #pragma unroll
            for (int in = 0; in < 8; in++) {
                asm volatile(
                    "mma.sync.aligned.m16n8k16.row.col.f32.f16.f16.f32 "
                    "{%0,%1,%2,%3}, {%4,%5,%6,%7}, {%8,%9}, {%0,%1,%2,%3};\n"
                    : "+f"(acc[0][in][0]), "+f"(acc[0][in][1]),
                      "+f"(acc[0][in][2]), "+f"(acc[0][in][3])
                    : "r"(a00.x), "r"(a08.x), "r"(a00.y), "r"(a08.y),
                      "r"(bv[in].x), "r"(bv[in].y));
                asm volatile(
                    "mma.sync.aligned.m16n8k16.row.col.f32.f16.f16.f32 "
                    "{%0,%1,%2,%3}, {%4,%5,%6,%7}, {%8,%9}, {%0,%1,%2,%3};\n"
                    : "+f"(acc[1][in][0]), "+f"(acc[1][in][1]),
                      "+f"(acc[1][in][2]), "+f"(acc[1][in][3])
                    : "r"(a16.x), "r"(a24.x), "r"(a16.y), "r"(a24.y),
                      "r"(bv[in].x), "r"(bv[in].y));
            }
        }
        __syncthreads();
    }
    #undef PREFETCH

    // ---- Epilogue: activations + Z*I combine via smem staging (proven) ----
    #define BSTRIDE 132
    float* Sa = (float*)smem;            // 32*132 floats
    float* Sb = Sa + 32 * BSTRIDE;

    if (warp_m == 0 || warp_m == 3) {
        float* St = (warp_m == 0) ? Sa : Sb;
        #pragma unroll
        for (int im = 0; im < 2; im++)
            #pragma unroll
            for (int in = 0; in < 8; in++)
                #pragma unroll
                for (int ci = 0; ci < 4; ci++) {
                    int r  = im * 16 + g4 + ((ci >> 1) << 3);
                    int cc = warp_n * 64 + in * 8 + (t4 << 1) + (ci & 1);
                    float v = acc[im][in][ci] + bias_s[warp_m * 32 + r];
                    v = (warp_m == 0) ? tanh_acc(v) : sigm(v);
                    St[r * BSTRIDE + cc] = v;
                }
    }
    __syncthreads();
    #pragma unroll
    for (int i = 0; i < 16; i++) {
        int e = tid + i * 256;
        int r = e >> 7, cc = e & 127;
        g_iz[((size_t)(b * COUT + oc0 + r)) * TT + t0 + cc] =
            Sa[r * BSTRIDE + cc] * Sb[r * BSTRIDE + cc];
    }
    __syncthreads();
    if (warp_m == 1 || warp_m == 2) {
        float* St = (warp_m == 1) ? Sa : Sb;
        #pragma unroll
        for (int im = 0; im < 2; im++)
            #pragma unroll
            for (int in = 0; in < 8; in++)
                #pragma unroll
                for (int ci = 0; ci < 4; ci++) {
                    int r  = im * 16 + g4 + ((ci >> 1) << 3);
                    int cc = warp_n * 64 + in * 8 + (t4 << 1) + (ci & 1);
                    St[r * BSTRIDE + cc] = sigm(acc[im][in][ci] + bias_s[warp_m * 32 + r]);
                }
    }
    __syncthreads();
    #pragma unroll
    for (int i = 0; i < 16; i++) {
        int e = tid + i * 256;
        int r = e >> 7, cc = e & 127;
        size_t gidx = ((size_t)(b * COUT + oc0 + r)) * TT + t0 + cc;
        g_f[gidx] = Sa[r * BSTRIDE + cc];
        g_o[gidx] = Sb[r * BSTRIDE + cc];
    }
    #undef BSTRIDE
}

// ---------------------------------------------------------------------------
// Kernel 4: linear recurrence scan. 256 threads/block, 16 elems/thread.
//   c_t = f_t * c_{t-1} + iz_t ;  H_t = o_t * c_t
// ---------------------------------------------------------------------------
__global__ __launch_bounds__(256)
void qrnn_scan(float* __restrict__ out)
{
    __shared__ float wa[8], wb[8];

    const int tid  = threadIdx.x;
    const int lane = tid & 31;
    const int wrp  = tid >> 5;
    const size_t my = (size_t)blockIdx.x * TT + tid * 16;

    float f[16], z[16];
    #pragma unroll
    for (int j = 0; j < 4; j++) {
        float4 vf = ((const float4*)(g_f  + my))[j];
        float4 vz = ((const float4*)(g_iz + my))[j];
        f[j*4+0] = vf.x; f[j*4+1] = vf.y; f[j*4+2] = vf.z; f[j*4+3] = vf.w;
        z[j*4+0] = vz.x; z[j*4+1] = vz.y; z[j*4+2] = vz.z; z[j*4+3] = vz.w;
    }

    float a = 1.f, bb = 0.f;
    #pragma unroll
    for (int j = 0; j < 16; j++) { a *= f[j]; bb = f[j] * bb + z[j]; }

    #pragma unroll
    for (int d = 1; d < 32; d <<= 1) {
        float ua = __shfl_up_sync(0xffffffffu, a,  d);
        float ub = __shfl_up_sync(0xffffffffu, bb, d);
        if (lane >= d) { bb = a * ub + bb; a = a * ua; }
    }
    if (lane == 31) { wa[wrp] = a; wb[wrp] = bb; }
    __syncthreads();
    float pb = 0.f;
    #pragma unroll
    for (int w = 0; w < 7; w++)
        if (w < wrp) pb = wa[w] * pb + wb[w];
    float ea = __shfl_up_sync(0xffffffffu, a,  1);
    float eb = __shfl_up_sync(0xffffffffu, bb, 1);
    if (lane == 0) { ea = 1.f; eb = 0.f; }
    float c = ea * pb + eb;              // carry into this chunk (c_init = 0)

    #pragma unroll
    for (int j = 0; j < 16; j++) { c = f[j] * c + z[j]; f[j] = c; }

    #pragma unroll
    for (int j = 0; j < 4; j++) {
        float4 vo = ((const float4*)(g_o + my))[j];
        float4 r;
        r.x = vo.x * f[j*4+0]; r.y = vo.y * f[j*4+1];
        r.z = vo.z * f[j*4+2]; r.w = vo.w * f[j*4+3];
        ((float4*)(out + my))[j] = r;
    }
}

extern "C" void kernel_launch(void* const* d_in, const int* in_sizes, int n_in,
                              void* d_out, int out_size)
{
    const float* x    = (const float*)d_in[0];  // [8, 256, 4096]
    const float* W    = (const float*)d_in[1];  // [1024, 256, 2]
    const float* bias = (const float*)d_in[2];  // [1024]
    float* out = (float*)d_out;                 // [8, 256, 4096]

    static int smem_set = 0;
    if (!smem_set) {
        cudaFuncSetAttribute(qrnn_gemm, cudaFuncAttributeMaxDynamicSharedMemorySize, GEMM_SMEM);
        smem_set = 1;
    }

    k_xprep<<<dim3(TT / 32, CIN / 32, BBATCH), 256>>>(x);
    k_wprep<<<dim3(NKT, 8), 256>>>(W);
    qrnn_gemm<<<dim3(BBATCH * TT / BN, 8), 256, GEMM_SMEM>>>(bias);
    qrnn_scan<<<BBATCH * COUT, 256>>>(out);
}

// round 10
// speedup vs baseline: 2.8132x; 1.1455x over previous
#include <cuda_runtime.h>
#include <cuda_fp16.h>
#include <cstdint>

// ---------------- problem constants ----------------
#define TT      4096
#define CIN     256
#define COUT    256
#define BBATCH  8
#define SGATE   (BBATCH*COUT*TT)     // 8388608

// GEMM tiling
#define BM      128
#define BN      128
#define BK      32
#define NKT     16                    // K=512 / 32
#define ROWB    96                    // smem row stride bytes (24 words) conflict-free
#define STAGEB  (2*BM*ROWB)           // 24576 bytes per stage (A + B)
#define NSTAGE  3
#define GEMM_SMEM (NSTAGE*STAGEB)     // 73728

// ---------------- scratch (__device__ globals; alloc-free rule) -------------
__device__ __align__(128) __half2 g_fz[SGATE];                  // (.x=f, .y=i*z) fp16
__device__ __align__(128) __half  g_o [SGATE];                  // o fp16
__device__ __align__(128) __half  xT  [(size_t)BBATCH*TT*CIN];  // [b][t][cin'] perm fp16
__device__ __align__(128) __half  Wp  [8*NKT*BM*BK];            // [y][kt][m][k'] perm fp16

// ---------------- helpers ----------------
__device__ __forceinline__ float sigm(float v)    { return 1.f / (1.f + __expf(-v)); }
__device__ __forceinline__ float tanh_acc(float v){ return 2.f / (1.f + __expf(-2.f*v)) - 1.f; }
__device__ __forceinline__ uint32_t smem_u32(const void* p) {
    uint32_t a;
    asm("{ .reg .u64 t; cvta.to.shared.u64 t, %1; cvt.u32.u64 %0, t; }" : "=r"(a) : "l"(p));
    return a;
}
// inverse of the frag interleave: dest slot j' (0..15) -> source k-in-16
__device__ __forceinline__ int invp(int jp) {
    int t4 = jp >> 2, pos = jp & 3;
    return 2 * t4 + (pos & 1) + 8 * (pos >> 1);
}

// ---------------------------------------------------------------------------
// Pre-kernel 1: x [b][cin][t] -> xT [b][t][cin'] fp16, k-interleaved per 16
// ---------------------------------------------------------------------------
__global__ __launch_bounds__(256)
void k_xprep(const float* __restrict__ x)
{
    __shared__ float s[32][33];
    const int t0 = blockIdx.x * 32, c0 = blockIdx.y * 32, b = blockIdx.z;
    const int lane = threadIdx.x & 31;

    #pragma unroll
    for (int rr = threadIdx.x >> 5; rr < 32; rr += 8)
        s[rr][lane] = x[((size_t)(b * CIN + c0 + rr)) * TT + t0 + lane];
    __syncthreads();

    #pragma unroll
    for (int i = 0; i < 2; i++) {
        int sl = threadIdx.x + i * 256;       // 512 u32 slots: 32 trow x 16
        int trow = sl >> 4, ms = sl & 15;
        int grp = ms >> 3, jp = (2 * ms) & 15;
        int c0s = grp * 16 + invp(jp);
        int c1s = grp * 16 + invp(jp + 1);
        __half2 v = __floats2half2_rn(s[c0s][trow], s[c1s][trow]);
        ((__half2*)xT)[(((size_t)(b * TT + t0 + trow)) * CIN + c0 >> 1) + ms] = v;
    }
}

// ---------------------------------------------------------------------------
// Pre-kernel 2: W [1024][256][2] -> Wp [y][kt][m][k'] fp16 (permute+interleave)
// ---------------------------------------------------------------------------
__global__ __launch_bounds__(256)
void k_wprep(const float* __restrict__ W)
{
    const int kt = blockIdx.x, y = blockIdx.y;
    __half2* dst = (__half2*)(Wp + ((size_t)(y * NKT + kt) << 12));
    #pragma unroll
    for (int i = 0; i < 8; i++) {
        int sl = threadIdx.x + i * 256;       // 2048 u32 slots: 128 m x 16
        int m = sl >> 4, ms = sl & 15;
        int grp = ms >> 3, jp = (2 * ms) & 15;
        int wrow = (m >> 5) * 256 + y * 32 + (m & 31);
        int kk0 = kt * 32 + grp * 16 + invp(jp);
        int kk1 = kt * 32 + grp * 16 + invp(jp + 1);
        float v0 = W[wrow * 512 + ((kk0 & 255) << 1) + (kk0 >> 8)];
        float v1 = W[wrow * 512 + ((kk1 & 255) << 1) + (kk1 >> 8)];
        dst[sl] = __floats2half2_rn(v0, v1);
    }
}

// ---------------------------------------------------------------------------
// Kernel 3: 3-stage pipelined fp16 mma.sync m16n8k16 GEMM + fused activations.
//   One __syncthreads per k-tile; single-round 4-buffer epilogue.
// ---------------------------------------------------------------------------
__global__ __launch_bounds__(256, 2)
void qrnn_gemm(const float* __restrict__ bias)
{
    extern __shared__ char smem[];
    __shared__ float bias_s[BM];

    const int tid    = threadIdx.x;
    const int lane   = tid & 31;
    const int wid    = tid >> 5;
    const int warp_m = wid >> 1;         // gate 0:Z 1:F 2:O 3:I
    const int warp_n = wid & 1;
    const int g4     = lane >> 2;
    const int t4     = lane & 3;

    const int y   = blockIdx.y;
    const int oc0 = y * 32;
    const int b   = blockIdx.x >> 5;
    const int t0  = (blockIdx.x & 31) * BN;

    if (tid < BM)
        bias_s[tid] = bias[(tid >> 5) * 256 + oc0 + (tid & 31)];

    float acc[2][8][4];
    #pragma unroll
    for (int im = 0; im < 2; im++)
        #pragma unroll
        for (int in = 0; in < 8; in++)
            #pragma unroll
            for (int ci = 0; ci < 4; ci++) acc[im][in][ci] = 0.f;

    // per-thread cp.async coords: 1024 16B chunks (A 512 + B 512), 4 per thread
    #define PREFETCH(KT, BUF) do {                                              \
        const int kt_ = (KT);                                                   \
        char* stA_ = smem + (BUF) * STAGEB;                                     \
        char* stB_ = stA_ + BM * ROWB;                                          \
        const __half* wc_ = Wp + ((size_t)(y * NKT + kt_) << 12);               \
        const int tap_  = (kt_ < 8) ? 1 : 0;                                    \
        const int cin0_ = (kt_ & 7) * 32;                                       \
        _Pragma("unroll")                                                       \
        for (int i_ = 0; i_ < 4; i_++) {                                        \
            int u_ = tid + i_ * 256;                                            \
            int idx_ = u_ & 511, r_ = idx_ >> 2, cu_ = idx_ & 3;                \
            if (u_ < 512) {                                                     \
                uint32_t da_ = smem_u32(stA_ + r_ * ROWB + cu_ * 16);           \
                asm volatile("cp.async.cg.shared.global [%0], [%1], 16;"        \
                    :: "r"(da_), "l"(wc_ + r_ * 32 + cu_ * 8) : "memory");      \
            } else {                                                            \
                uint32_t db_ = smem_u32(stB_ + r_ * ROWB + cu_ * 16);           \
                int tg_ = t0 + r_ - tap_;                                       \
                int sz_ = (tg_ >= 0) ? 16 : 0;                                  \
                const __half* src_ = xT + ((size_t)(b * TT + tg_) * CIN + cin0_ + cu_ * 8); \
                asm volatile("cp.async.cg.shared.global [%0], [%1], 16, %2;"    \
                    :: "r"(db_), "l"(src_), "r"(sz_) : "memory");               \
            }                                                                   \
        }                                                                       \
        asm volatile("cp.async.commit_group;" ::: "memory");                    \
    } while (0)

    PREFETCH(0, 0);
    PREFETCH(1, 1);

    #pragma unroll 1
    for (int kt = 0; kt < NKT; kt++) {
        if (kt == NKT - 1) asm volatile("cp.async.wait_group 0;" ::: "memory");
        else               asm volatile("cp.async.wait_group 1;" ::: "memory");
        __syncthreads();   // stage kt visible; all reads of stage kt-1 done
        if (kt + 2 < NKT) PREFETCH(kt + 2, (kt + 2) % NSTAGE);

        const char* As = smem + (kt % NSTAGE) * STAGEB;
        const char* Bs = As + BM * ROWB;
        const int row0 = warp_m * 32 + g4;
        const int col0 = warp_n * 64 + g4;

        #pragma unroll
        for (int s = 0; s < 2; s++) {
            const int kb = s * 32 + t4 * 8;
            uint2 a00 = *(const uint2*)(As + (row0     ) * ROWB + kb);
            uint2 a08 = *(const uint2*)(As + (row0 +  8) * ROWB + kb);
            uint2 a16 = *(const uint2*)(As + (row0 + 16) * ROWB + kb);
            uint2 a24 = *(const uint2*)(As + (row0 + 24) * ROWB + kb);
            uint2 bv[8];
            #pragma unroll
            for (int in = 0; in < 8; in++)
                bv[in] = *(const uint2*)(Bs + (col0 + in * 8) * ROWB + kb);
            #pragma unroll
            for (int in = 0; in < 8; in++) {
                asm volatile(
                    "mma.sync.aligned.m16n8k16.row.col.f32.f16.f16.f32 "
                    "{%0,%1,%2,%3}, {%4,%5,%6,%7}, {%8,%9}, {%0,%1,%2,%3};\n"
                    : "+f"(acc[0][in][0]), "+f"(acc[0][in][1]),
                      "+f"(acc[0][in][2]), "+f"(acc[0][in][3])
                    : "r"(a00.x), "r"(a08.x), "r"(a00.y), "r"(a08.y),
                      "r"(bv[in].x), "r"(bv[in].y));
                asm volatile(
                    "mma.sync.aligned.m16n8k16.row.col.f32.f16.f16.f32 "
                    "{%0,%1,%2,%3}, {%4,%5,%6,%7}, {%8,%9}, {%0,%1,%2,%3};\n"
                    : "+f"(acc[1][in][0]), "+f"(acc[1][in][1]),
                      "+f"(acc[1][in][2]), "+f"(acc[1][in][3])
                    : "r"(a16.x), "r"(a24.x), "r"(a16.y), "r"(a24.y),
                      "r"(bv[in].x), "r"(bv[in].y));
            }
        }
    }
    #undef PREFETCH
    __syncthreads();   // all MMA reads done before smem reuse as staging

    // ---- Epilogue: single round. 4 gate buffers (Z,F,O,I), one barrier. ----
    #define BSTRIDE 132
    {
        float* St = (float*)smem + warp_m * (32 * BSTRIDE);
        #pragma unroll
        for (int im = 0; im < 2; im++)
            #pragma unroll
            for (int in = 0; in < 8; in++)
                #pragma unroll
                for (int ci = 0; ci < 4; ci++) {
                    int r  = im * 16 + g4 + ((ci >> 1) << 3);
                    int cc = warp_n * 64 + in * 8 + (t4 << 1) + (ci & 1);
                    float v = acc[im][in][ci] + bias_s[warp_m * 32 + r];
                    v = (warp_m == 0) ? tanh_acc(v) : sigm(v);
                    St[r * BSTRIDE + cc] = v;
                }
    }
    __syncthreads();
    {
        const float* Sz = (float*)smem;
        const float* Sf = Sz + 32 * BSTRIDE;
        const float* So = Sz + 2 * (32 * BSTRIDE);
        const float* Si = Sz + 3 * (32 * BSTRIDE);
        #pragma unroll
        for (int i = 0; i < 16; i++) {
            int e = tid + i * 256;
            int r = e >> 7, cc = e & 127;
            int sidx = r * BSTRIDE + cc;
            size_t gidx = ((size_t)(b * COUT + oc0 + r)) * TT + t0 + cc;
            g_fz[gidx] = __floats2half2_rn(Sf[sidx], Sz[sidx] * Si[sidx]);
            g_o [gidx] = __float2half_rn(So[sidx]);
        }
    }
    #undef BSTRIDE
}

// ---------------------------------------------------------------------------
// Kernel 4: linear recurrence scan over fp16 packed gates.
//   c_t = f_t * c_{t-1} + iz_t ;  H_t = o_t * c_t
// ---------------------------------------------------------------------------
__global__ __launch_bounds__(256)
void qrnn_scan(float* __restrict__ out)
{
    __shared__ float wa[8], wb[8];

    const int tid  = threadIdx.x;
    const int lane = tid & 31;
    const int wrp  = tid >> 5;
    const size_t my = (size_t)blockIdx.x * TT + tid * 16;

    float f[16], z[16];
    #pragma unroll
    for (int q = 0; q < 4; q++) {
        uint4 v = ((const uint4*)(g_fz + my))[q];
        float2 p0 = __half22float2(*(const __half2*)&v.x);
        float2 p1 = __half22float2(*(const __half2*)&v.y);
        float2 p2 = __half22float2(*(const __half2*)&v.z);
        float2 p3 = __half22float2(*(const __half2*)&v.w);
        f[q*4+0] = p0.x; z[q*4+0] = p0.y;
        f[q*4+1] = p1.x; z[q*4+1] = p1.y;
        f[q*4+2] = p2.x; z[q*4+2] = p2.y;
        f[q*4+3] = p3.x; z[q*4+3] = p3.y;
    }

    float a = 1.f, bb = 0.f;
    #pragma unroll
    for (int j = 0; j < 16; j++) { a *= f[j]; bb = f[j] * bb + z[j]; }

    #pragma unroll
    for (int d = 1; d < 32; d <<= 1) {
        float ua = __shfl_up_sync(0xffffffffu, a,  d);
        float ub = __shfl_up_sync(0xffffffffu, bb, d);
        if (lane >= d) { bb = a * ub + bb; a = a * ua; }
    }
    if (lane == 31) { wa[wrp] = a; wb[wrp] = bb; }
    __syncthreads();
    float pb = 0.f;
    #pragma unroll
    for (int w = 0; w < 7; w++)
        if (w < wrp) pb = wa[w] * pb + wb[w];
    float ea = __shfl_up_sync(0xffffffffu, a,  1);
    float eb = __shfl_up_sync(0xffffffffu, bb, 1);
    if (lane == 0) { ea = 1.f; eb = 0.f; }
    float c = ea * pb + eb;              // carry into this chunk (c_init = 0)

    #pragma unroll
    for (int j = 0; j < 16; j++) { c = f[j] * c + z[j]; f[j] = c; }

    // o gates: 16 halves = 32B = two uint4
    uint4 o0 = ((const uint4*)(g_o + my))[0];
    uint4 o1 = ((const uint4*)(g_o + my))[1];
    const __half2* oh = (const __half2*)&o0;   // o0,o1 contiguous in regs? use per-part
    float ov[16];
    {
        const uint32_t* w0 = (const uint32_t*)&o0;
        const uint32_t* w1 = (const uint32_t*)&o1;
        #pragma unroll
        for (int q = 0; q < 4; q++) {
            float2 p = __half22float2(*(const __half2*)&w0[q]);
            ov[q*2+0] = p.x; ov[q*2+1] = p.y;
        }
        #pragma unroll
        for (int q = 0; q < 4; q++) {
            float2 p = __half22float2(*(const __half2*)&w1[q]);
            ov[8+q*2+0] = p.x; ov[8+q*2+1] = p.y;
        }
    }
    (void)oh;

    #pragma unroll
    for (int j = 0; j < 4; j++) {
        float4 r;
        r.x = ov[j*4+0] * f[j*4+0]; r.y = ov[j*4+1] * f[j*4+1];
        r.z = ov[j*4+2] * f[j*4+2]; r.w = ov[j*4+3] * f[j*4+3];
        ((float4*)(out + my))[j] = r;
    }
}

extern "C" void kernel_launch(void* const* d_in, const int* in_sizes, int n_in,
                              void* d_out, int out_size)
{
    const float* x    = (const float*)d_in[0];  // [8, 256, 4096]
    const float* W    = (const float*)d_in[1];  // [1024, 256, 2]
    const float* bias = (const float*)d_in[2];  // [1024]
    float* out = (float*)d_out;                 // [8, 256, 4096]

    static int smem_set = 0;
    if (!smem_set) {
        cudaFuncSetAttribute(qrnn_gemm, cudaFuncAttributeMaxDynamicSharedMemorySize, GEMM_SMEM);
        smem_set = 1;
    }

    k_xprep<<<dim3(TT / 32, CIN / 32, BBATCH), 256>>>(x);
    k_wprep<<<dim3(NKT, 8), 256>>>(W);
    qrnn_gemm<<<dim3(BBATCH * TT / BN, 8), 256, GEMM_SMEM>>>(bias);
    qrnn_scan<<<BBATCH * COUT, 256>>>(out);
}

// round 11
// speedup vs baseline: 2.9086x; 1.0339x over previous
#include <cuda_runtime.h>
#include <cuda_fp16.h>
#include <cstdint>

// ---------------- problem constants ----------------
#define TT      4096
#define CIN     256
#define COUT    256
#define BBATCH  8
#define SGATE   (BBATCH*COUT*TT)     // 8388608

// GEMM tiling
#define BM      128
#define BN      128
#define BK      32
#define NKT     16                    // K=512 / 32
#define ROWB    96                    // smem row stride bytes (24 words) conflict-free
#define STAGEB  (2*BM*ROWB)           // 24576 bytes per stage (A + B)
#define NSTAGE  4
#define GEMM_SMEM (NSTAGE*STAGEB)     // 98304

// ---------------- scratch (__device__ globals; alloc-free rule) -------------
__device__ __align__(128) __half2 g_fz[SGATE];                  // (.x=f, .y=i*z) fp16
__device__ __align__(128) __half  g_o [SGATE];                  // o fp16
__device__ __align__(128) __half  xT  [(size_t)BBATCH*TT*CIN];  // [b][t][cin'] perm fp16
__device__ __align__(128) __half  Wp  [8*NKT*BM*BK];            // [y][kt][m][k'] perm fp16

// ---------------- helpers ----------------
__device__ __forceinline__ float sigm(float v)    { return 1.f / (1.f + __expf(-v)); }
__device__ __forceinline__ float tanh_acc(float v){ return 2.f / (1.f + __expf(-2.f*v)) - 1.f; }
__device__ __forceinline__ uint32_t smem_u32(const void* p) {
    uint32_t a;
    asm("{ .reg .u64 t; cvta.to.shared.u64 t, %1; cvt.u32.u64 %0, t; }" : "=r"(a) : "l"(p));
    return a;
}
// inverse of the frag interleave: dest slot j' (0..15) -> source k-in-16
__device__ __forceinline__ int invp(int jp) {
    int t4 = jp >> 2, pos = jp & 3;
    return 2 * t4 + (pos & 1) + 8 * (pos >> 1);
}

// ---------------------------------------------------------------------------
// Pre-kernel 1: x [b][cin][t] -> xT [b][t][cin'] fp16, k-interleaved per 16
// ---------------------------------------------------------------------------
__global__ __launch_bounds__(256)
void k_xprep(const float* __restrict__ x)
{
    __shared__ float s[32][33];
    const int t0 = blockIdx.x * 32, c0 = blockIdx.y * 32, b = blockIdx.z;
    const int lane = threadIdx.x & 31;

    #pragma unroll
    for (int rr = threadIdx.x >> 5; rr < 32; rr += 8)
        s[rr][lane] = x[((size_t)(b * CIN + c0 + rr)) * TT + t0 + lane];
    __syncthreads();

    #pragma unroll
    for (int i = 0; i < 2; i++) {
        int sl = threadIdx.x + i * 256;       // 512 u32 slots: 32 trow x 16
        int trow = sl >> 4, ms = sl & 15;
        int grp = ms >> 3, jp = (2 * ms) & 15;
        int c0s = grp * 16 + invp(jp);
        int c1s = grp * 16 + invp(jp + 1);
        __half2 v = __floats2half2_rn(s[c0s][trow], s[c1s][trow]);
        ((__half2*)xT)[(((size_t)(b * TT + t0 + trow)) * CIN + c0 >> 1) + ms] = v;
    }
}

// ---------------------------------------------------------------------------
// Pre-kernel 2: W [1024][256][2] -> Wp [y][kt][m][k'] fp16 (permute+interleave)
// ---------------------------------------------------------------------------
__global__ __launch_bounds__(256)
void k_wprep(const float* __restrict__ W)
{
    const int kt = blockIdx.x, y = blockIdx.y;
    __half2* dst = (__half2*)(Wp + ((size_t)(y * NKT + kt) << 12));
    #pragma unroll
    for (int i = 0; i < 8; i++) {
        int sl = threadIdx.x + i * 256;       // 2048 u32 slots: 128 m x 16
        int m = sl >> 4, ms = sl & 15;
        int grp = ms >> 3, jp = (2 * ms) & 15;
        int wrow = (m >> 5) * 256 + y * 32 + (m & 31);
        int kk0 = kt * 32 + grp * 16 + invp(jp);
        int kk1 = kt * 32 + grp * 16 + invp(jp + 1);
        float v0 = W[wrow * 512 + ((kk0 & 255) << 1) + (kk0 >> 8)];
        float v1 = W[wrow * 512 + ((kk1 & 255) << 1) + (kk1 >> 8)];
        dst[sl] = __floats2half2_rn(v0, v1);
    }
}

// ---------------------------------------------------------------------------
// Kernel 3: 4-stage pipelined fp16 mma.sync m16n8k16 GEMM + fused activations.
//   2-3 cp.async groups in flight at steady state; one barrier per k-tile.
// ---------------------------------------------------------------------------
__global__ __launch_bounds__(256, 2)
void qrnn_gemm(const float* __restrict__ bias)
{
    extern __shared__ char smem[];
    __shared__ float bias_s[BM];

    const int tid    = threadIdx.x;
    const int lane   = tid & 31;
    const int wid    = tid >> 5;
    const int warp_m = wid >> 1;         // gate 0:Z 1:F 2:O 3:I
    const int warp_n = wid & 1;
    const int g4     = lane >> 2;
    const int t4     = lane & 3;

    const int y   = blockIdx.y;
    const int oc0 = y * 32;
    const int b   = blockIdx.x >> 5;
    const int t0  = (blockIdx.x & 31) * BN;

    if (tid < BM)
        bias_s[tid] = bias[(tid >> 5) * 256 + oc0 + (tid & 31)];

    float acc[2][8][4];
    #pragma unroll
    for (int im = 0; im < 2; im++)
        #pragma unroll
        for (int in = 0; in < 8; in++)
            #pragma unroll
            for (int ci = 0; ci < 4; ci++) acc[im][in][ci] = 0.f;

    // per-thread cp.async coords: 1024 16B chunks (A 512 + B 512), 4 per thread
    #define PREFETCH(KT, BUF) do {                                              \
        const int kt_ = (KT);                                                   \
        char* stA_ = smem + (BUF) * STAGEB;                                     \
        char* stB_ = stA_ + BM * ROWB;                                          \
        const __half* wc_ = Wp + ((size_t)(y * NKT + kt_) << 12);               \
        const int tap_  = (kt_ < 8) ? 1 : 0;                                    \
        const int cin0_ = (kt_ & 7) * 32;                                       \
        _Pragma("unroll")                                                       \
        for (int i_ = 0; i_ < 4; i_++) {                                        \
            int u_ = tid + i_ * 256;                                            \
            int idx_ = u_ & 511, r_ = idx_ >> 2, cu_ = idx_ & 3;                \
            if (u_ < 512) {                                                     \
                uint32_t da_ = smem_u32(stA_ + r_ * ROWB + cu_ * 16);           \
                asm volatile("cp.async.cg.shared.global [%0], [%1], 16;"        \
                    :: "r"(da_), "l"(wc_ + r_ * 32 + cu_ * 8) : "memory");      \
            } else {                                                            \
                uint32_t db_ = smem_u32(stB_ + r_ * ROWB + cu_ * 16);           \
                int tg_ = t0 + r_ - tap_;                                       \
                int sz_ = (tg_ >= 0) ? 16 : 0;                                  \
                const __half* src_ = xT + ((size_t)(b * TT + tg_) * CIN + cin0_ + cu_ * 8); \
                asm volatile("cp.async.cg.shared.global [%0], [%1], 16, %2;"    \
                    :: "r"(db_), "l"(src_), "r"(sz_) : "memory");               \
            }                                                                   \
        }                                                                       \
        asm volatile("cp.async.commit_group;" ::: "memory");                    \
    } while (0)

    PREFETCH(0, 0);
    PREFETCH(1, 1);
    PREFETCH(2, 2);

    #pragma unroll 1
    for (int kt = 0; kt < NKT; kt++) {
        // stage kt must be complete; keep deeper prefetches in flight
        if      (kt <= NKT - 3) asm volatile("cp.async.wait_group 2;" ::: "memory");
        else if (kt == NKT - 2) asm volatile("cp.async.wait_group 1;" ::: "memory");
        else                    asm volatile("cp.async.wait_group 0;" ::: "memory");
        __syncthreads();   // stage kt visible to all; stage (kt+3)&3 free for reuse
        if (kt + 3 < NKT) PREFETCH(kt + 3, (kt + 3) & 3);

        const char* As = smem + (kt & 3) * STAGEB;
        const char* Bs = As + BM * ROWB;
        const int row0 = warp_m * 32 + g4;
        const int col0 = warp_n * 64 + g4;

        #pragma unroll
        for (int s = 0; s < 2; s++) {
            const int kb = s * 32 + t4 * 8;
            uint2 a00 = *(const uint2*)(As + (row0     ) * ROWB + kb);
            uint2 a08 = *(const uint2*)(As + (row0 +  8) * ROWB + kb);
            uint2 a16 = *(const uint2*)(As + (row0 + 16) * ROWB + kb);
            uint2 a24 = *(const uint2*)(As + (row0 + 24) * ROWB + kb);
            uint2 bv[8];
            #pragma unroll
            for (int in = 0; in < 8; in++)
                bv[in] = *(const uint2*)(Bs + (col0 + in * 8) * ROWB + kb);
            #pragma unroll
            for (int in = 0; in < 8; in++) {
                asm volatile(
                    "mma.sync.aligned.m16n8k16.row.col.f32.f16.f16.f32 "
                    "{%0,%1,%2,%3}, {%4,%5,%6,%7}, {%8,%9}, {%0,%1,%2,%3};\n"
                    : "+f"(acc[0][in][0]), "+f"(acc[0][in][1]),
                      "+f"(acc[0][in][2]), "+f"(acc[0][in][3])
                    : "r"(a00.x), "r"(a08.x), "r"(a00.y), "r"(a08.y),
                      "r"(bv[in].x), "r"(bv[in].y));
                asm volatile(
                    "mma.sync.aligned.m16n8k16.row.col.f32.f16.f16.f32 "
                    "{%0,%1,%2,%3}, {%4,%5,%6,%7}, {%8,%9}, {%0,%1,%2,%3};\n"
                    : "+f"(acc[1][in][0]), "+f"(acc[1][in][1]),
                      "+f"(acc[1][in][2]), "+f"(acc[1][in][3])
                    : "r"(a16.x), "r"(a24.x), "r"(a16.y), "r"(a24.y),
                      "r"(bv[in].x), "r"(bv[in].y));
            }
        }
    }
    #undef PREFETCH
    __syncthreads();   // all MMA reads done before smem reuse as staging

    // ---- Epilogue: single round. 4 gate buffers (Z,F,O,I), one barrier. ----
    #define BSTRIDE 132
    {
        float* St = (float*)smem + warp_m * (32 * BSTRIDE);
        #pragma unroll
        for (int im = 0; im < 2; im++)
            #pragma unroll
            for (int in = 0; in < 8; in++)
                #pragma unroll
                for (int ci = 0; ci < 4; ci++) {
                    int r  = im * 16 + g4 + ((ci >> 1) << 3);
                    int cc = warp_n * 64 + in * 8 + (t4 << 1) + (ci & 1);
                    float v = acc[im][in][ci] + bias_s[warp_m * 32 + r];
                    v = (warp_m == 0) ? tanh_acc(v) : sigm(v);
                    St[r * BSTRIDE + cc] = v;
                }
    }
    __syncthreads();
    {
        const float* Sz = (float*)smem;
        const float* Sf = Sz + 32 * BSTRIDE;
        const float* So = Sz + 2 * (32 * BSTRIDE);
        const float* Si = Sz + 3 * (32 * BSTRIDE);
        #pragma unroll
        for (int i = 0; i < 16; i++) {
            int e = tid + i * 256;
            int r = e >> 7, cc = e & 127;
            int sidx = r * BSTRIDE + cc;
            size_t gidx = ((size_t)(b * COUT + oc0 + r)) * TT + t0 + cc;
            g_fz[gidx] = __floats2half2_rn(Sf[sidx], Sz[sidx] * Si[sidx]);
            g_o [gidx] = __float2half_rn(So[sidx]);
        }
    }
    #undef BSTRIDE
}

// ---------------------------------------------------------------------------
// Kernel 4: linear recurrence scan over fp16 packed gates.
//   512 threads/block, 8 elems/thread. c_t = f*c + iz ; H = o*c
// ---------------------------------------------------------------------------
__global__ __launch_bounds__(512)
void qrnn_scan(float* __restrict__ out)
{
    __shared__ float wa[16], wb[16];

    const int tid  = threadIdx.x;
    const int lane = tid & 31;
    const int wrp  = tid >> 5;
    const size_t my = (size_t)blockIdx.x * TT + tid * 8;

    float f[8], z[8];
    #pragma unroll
    for (int q = 0; q < 2; q++) {
        uint4 v = ((const uint4*)(g_fz + my))[q];
        float2 p0 = __half22float2(*(const __half2*)&v.x);
        float2 p1 = __half22float2(*(const __half2*)&v.y);
        float2 p2 = __half22float2(*(const __half2*)&v.z);
        float2 p3 = __half22float2(*(const __half2*)&v.w);
        f[q*4+0] = p0.x; z[q*4+0] = p0.y;
        f[q*4+1] = p1.x; z[q*4+1] = p1.y;
        f[q*4+2] = p2.x; z[q*4+2] = p2.y;
        f[q*4+3] = p3.x; z[q*4+3] = p3.y;
    }

    float a = 1.f, bb = 0.f;
    #pragma unroll
    for (int j = 0; j < 8; j++) { a *= f[j]; bb = f[j] * bb + z[j]; }

    #pragma unroll
    for (int d = 1; d < 32; d <<= 1) {
        float ua = __shfl_up_sync(0xffffffffu, a,  d);
        float ub = __shfl_up_sync(0xffffffffu, bb, d);
        if (lane >= d) { bb = a * ub + bb; a = a * ua; }
    }
    if (lane == 31) { wa[wrp] = a; wb[wrp] = bb; }
    __syncthreads();
    float pb = 0.f;
    #pragma unroll
    for (int w = 0; w < 15; w++)
        if (w < wrp) pb = wa[w] * pb + wb[w];
    float ea = __shfl_up_sync(0xffffffffu, a,  1);
    float eb = __shfl_up_sync(0xffffffffu, bb, 1);
    if (lane == 0) { ea = 1.f; eb = 0.f; }
    float c = ea * pb + eb;              // carry into this chunk (c_init = 0)

    #pragma unroll
    for (int j = 0; j < 8; j++) { c = f[j] * c + z[j]; f[j] = c; }

    // o gates: 8 halves = 16B = one uint4
    uint4 ov4 = ((const uint4*)(g_o + my))[0];
    float ov[8];
    {
        const uint32_t* w0 = (const uint32_t*)&ov4;
        #pragma unroll
        for (int q = 0; q < 4; q++) {
            float2 p = __half22float2(*(const __half2*)&w0[q]);
            ov[q*2+0] = p.x; ov[q*2+1] = p.y;
        }
    }

    #pragma unroll
    for (int j = 0; j < 2; j++) {
        float4 r;
        r.x = ov[j*4+0] * f[j*4+0]; r.y = ov[j*4+1] * f[j*4+1];
        r.z = ov[j*4+2] * f[j*4+2]; r.w = ov[j*4+3] * f[j*4+3];
        ((float4*)(out + my))[j] = r;
    }
}

extern "C" void kernel_launch(void* const* d_in, const int* in_sizes, int n_in,
                              void* d_out, int out_size)
{
    const float* x    = (const float*)d_in[0];  // [8, 256, 4096]
    const float* W    = (const float*)d_in[1];  // [1024, 256, 2]
    const float* bias = (const float*)d_in[2];  // [1024]
    float* out = (float*)d_out;                 // [8, 256, 4096]

    static int smem_set = 0;
    if (!smem_set) {
        cudaFuncSetAttribute(qrnn_gemm, cudaFuncAttributeMaxDynamicSharedMemorySize, GEMM_SMEM);
        smem_set = 1;
    }

    k_xprep<<<dim3(TT / 32, CIN / 32, BBATCH), 256>>>(x);
    k_wprep<<<dim3(NKT, 8), 256>>>(W);
    qrnn_gemm<<<dim3(BBATCH * TT / BN, 8), 256, GEMM_SMEM>>>(bias);
    qrnn_scan<<<BBATCH * COUT, 512>>>(out);
}